// round 6
// baseline (speedup 1.0000x reference)
#include <cuda_runtime.h>
#include <cuda_bf16.h>

// ---------------- problem constants ----------------
#define BB   16384            // batch
#define HH   256              // hidden
#define SS   4                // feature
#define TOBS 16               // encoder timesteps
#define TOUT 16               // decoder timesteps
#define BH   (BB * HH)        // 4,194,304

// ---------------- GEMM tiling ----------------
#define MT   64               // batch rows per block
#define NT   64               // per-gate cols per block (block covers 4*NT gate cols)
#define KT   16               // k tile
#define NTH  256              // threads per block

// ---------------- packed f32x2 helpers ----------------
#define FMA_F32X2(d, a, b) \
    asm("fma.rn.f32x2 %0, %1, %2, %0;" : "+l"(d) : "l"(a), "l"(b))
#define PACK_F32X2(out, lo, hi) \
    asm("mov.b64 %0, {%1, %2};" : "=l"(out) : "r"(__float_as_uint(lo)), "r"(__float_as_uint(hi)))
#define UNPACK_F32X2(lo, hi, in) \
    asm("mov.b64 {%0, %1}, %2;" : "=r"(lo), "=r"(hi) : "l"(in))

// ---------------- device scratch (allocation-free rule: __device__ globals) ----
__device__ float g_eh[2][2][BH];   // encoder h ping-pong [net][p]
__device__ float g_ec[2][BH];      // encoder c (in-place safe)
__device__ float g_dh[2][2][BH];   // decoder h ping-pong
__device__ float g_dc[2][BH];      // decoder c
__device__ float g_dx[2][BB * SS]; // decoder feedback inputs

struct Net {
    const float* __restrict__ Wih;   // [1024,4]
    const float* __restrict__ Whh;   // [1024,256]
    const float* __restrict__ bih;   // [1024]
    const float* __restrict__ bhh;   // [1024]
    const float* __restrict__ x;     // input rows
    int xstride;                     // floats between consecutive batch rows
    const float* __restrict__ h_in;  // [B,H]
    float* __restrict__ c;           // [B,H] in-place
    float* __restrict__ h_out;       // [B,H]
};

__device__ __forceinline__ float sigf(float x) {
    return 1.0f / (1.0f + __expf(-x));
}
__device__ __forceinline__ float tanh_acc(float x) {
    // 2*sigmoid(2x)-1 : EX2+RCP, abs err ~1e-7, saturates to +/-1 correctly
    return 2.0f / (1.0f + __expf(-2.0f * x)) - 1.0f;
}

// ================= fused LSTM step: G = h@Whh^T + x@Wih^T + b ; update c,h ===
// Packed-f32x2 GEMM: 32 FFMA2 per kk per thread, double-buffered smem,
// one __syncthreads per k-tile, global loads prefetched into registers.
__global__ void __launch_bounds__(NTH, 2)
lstm_step_kernel(Net n0, Net n1)
{
    Net P = (blockIdx.z == 0) ? n0 : n1;

    __shared__ float              Ws[2][KT][4 * NT];   // 2 x 16KB  [buf][k][gatecol]
    __shared__ unsigned long long Hs2[2][KT][MT];      // 2 x  8KB  [buf][k][m] = (h,h)
    __shared__ float4 WihS[4 * NT];
    __shared__ float  biasS[4 * NT];
    __shared__ float4 Xs[MT];

    const int tid = threadIdx.x;
    const int tx  = tid & 15;          // n group (4 cols per gate)
    const int ty  = tid >> 4;          // m group (4 rows)
    const int m0  = blockIdx.y * MT;
    const int nb0 = blockIdx.x * NT;

    const int gsel = tid >> 6;               // gate 0..3
    const int col  = tid & 63;               // col within gate tile
    const int j    = gsel * 256 + nb0 + col; // global gate column

    // ---- prologue: small operands ----
    WihS[tid]  = *(const float4*)(P.Wih + j * 4);
    biasS[tid] = P.bih[j] + P.bhh[j];
    if (tid < MT) {
        Xs[tid] = *(const float4*)(P.x + (size_t)(m0 + tid) * P.xstride);
    }

    const float* wr = P.Whh + (size_t)j * HH;     // this thread stages gate col j
    const int hr = tid & 63;                      // h row for staging
    const int kq = tid >> 6;                      // k quarter
    const float* hrow = P.h_in + (size_t)(m0 + hr) * HH + kq * 4;

    // ---- prefetch + stage k-tile 0 ----
    float4 wreg[4];
    float4 hreg;
    #pragma unroll
    for (int q = 0; q < 4; q++) wreg[q] = *(const float4*)(wr + q * 4);
    hreg = *(const float4*)(hrow);

    #pragma unroll
    for (int q = 0; q < 4; q++) {
        Ws[0][q * 4 + 0][tid] = wreg[q].x;
        Ws[0][q * 4 + 1][tid] = wreg[q].y;
        Ws[0][q * 4 + 2][tid] = wreg[q].z;
        Ws[0][q * 4 + 3][tid] = wreg[q].w;
    }
    {
        float hv[4] = {hreg.x, hreg.y, hreg.z, hreg.w};
        #pragma unroll
        for (int e = 0; e < 4; e++) {
            unsigned long long pp;
            PACK_F32X2(pp, hv[e], hv[e]);
            Hs2[0][kq * 4 + e][hr] = pp;
        }
    }
    __syncthreads();

    unsigned long long acc2[4][8];
    #pragma unroll
    for (int a = 0; a < 4; a++)
        #pragma unroll
        for (int p = 0; p < 8; p++) acc2[a][p] = 0ull;

    for (int kt = 0; kt < HH / KT; kt++) {
        const int buf = kt & 1;

        // prefetch next k-tile from global while computing this one
        if (kt < HH / KT - 1) {
            const int k0n = (kt + 1) * KT;
            #pragma unroll
            for (int q = 0; q < 4; q++) wreg[q] = *(const float4*)(wr + k0n + q * 4);
            hreg = *(const float4*)(hrow + k0n);
        }

        #pragma unroll
        for (int kk = 0; kk < KT; kk++) {
            ulonglong2 hA = *(const ulonglong2*)&Hs2[buf][kk][ty * 4];
            ulonglong2 hB = *(const ulonglong2*)&Hs2[buf][kk][ty * 4 + 2];
            unsigned long long hp[4] = {hA.x, hA.y, hB.x, hB.y};
            unsigned long long wp[8];
            #pragma unroll
            for (int g = 0; g < 4; g++) {
                ulonglong2 w2 = *(const ulonglong2*)&Ws[buf][kk][g * 64 + tx * 4];
                wp[g * 2 + 0] = w2.x;
                wp[g * 2 + 1] = w2.y;
            }
            #pragma unroll
            for (int mi = 0; mi < 4; mi++)
                #pragma unroll
                for (int p = 0; p < 8; p++)
                    FMA_F32X2(acc2[mi][p], hp[mi], wp[p]);
        }

        // store prefetched tile into the other buffer
        if (kt < HH / KT - 1) {
            const int nb = buf ^ 1;
            #pragma unroll
            for (int q = 0; q < 4; q++) {
                Ws[nb][q * 4 + 0][tid] = wreg[q].x;
                Ws[nb][q * 4 + 1][tid] = wreg[q].y;
                Ws[nb][q * 4 + 2][tid] = wreg[q].z;
                Ws[nb][q * 4 + 3][tid] = wreg[q].w;
            }
            float hv[4] = {hreg.x, hreg.y, hreg.z, hreg.w};
            #pragma unroll
            for (int e = 0; e < 4; e++) {
                unsigned long long pp;
                PACK_F32X2(pp, hv[e], hv[e]);
                Hs2[nb][kq * 4 + e][hr] = pp;
            }
        }
        __syncthreads();
    }

    // ---- epilogue: add x@Wih^T + bias, apply LSTM cell, write c,h ----
    const int r0 = ty * 4;
    #pragma unroll
    for (int mi = 0; mi < 4; mi++) {
        const int b = m0 + r0 + mi;
        float4 xr = Xs[r0 + mi];
        float gate[4][4];
        #pragma unroll
        for (int g = 0; g < 4; g++) {
            #pragma unroll
            for (int q = 0; q < 2; q++) {
                unsigned int alo, ahi;
                UNPACK_F32X2(alo, ahi, acc2[mi][g * 2 + q]);
                #pragma unroll
                for (int half = 0; half < 2; half++) {
                    int e  = q * 2 + half;
                    int ln = g * 64 + tx * 4 + e;
                    float4 wi = WihS[ln];
                    float av = __uint_as_float(half ? ahi : alo);
                    gate[g][e] = av + biasS[ln]
                               + xr.x * wi.x + xr.y * wi.y + xr.z * wi.z + xr.w * wi.w;
                }
            }
        }
        float* cp = P.c + (size_t)b * HH + nb0 + tx * 4;
        float4 cold = *(const float4*)cp;
        float cv[4] = {cold.x, cold.y, cold.z, cold.w};
        float cn[4], hn[4];
        #pragma unroll
        for (int e = 0; e < 4; e++) {
            float ig = sigf(gate[0][e]);
            float fg = sigf(gate[1][e]);
            float gg = tanh_acc(gate[2][e]);
            float og = sigf(gate[3][e]);
            cn[e] = fg * cv[e] + ig * gg;
            hn[e] = og * tanh_acc(cn[e]);
        }
        *(float4*)cp = make_float4(cn[0], cn[1], cn[2], cn[3]);
        *(float4*)(P.h_out + (size_t)b * HH + nb0 + tx * 4)
            = make_float4(hn[0], hn[1], hn[2], hn[3]);
    }
}

// ================= zero-init encoder state =================
__global__ void zero_state_kernel(float* a, float* b, float* c, float* d)
{
    int i = blockIdx.x * blockDim.x + threadIdx.x;
    a[i] = 0.0f; b[i] = 0.0f; c[i] = 0.0f; d[i] = 0.0f;
}

// ======== combine encoder states into both decoders; seed feedback x ========
__global__ void combine_kernel(const float* __restrict__ speed,
                               const float* __restrict__ pos)
{
    int i = blockIdx.x * blockDim.x + threadIdx.x;
    float hv = g_eh[0][0][i] + g_eh[1][0][i];
    float cv = g_ec[0][i] + g_ec[1][i];
    g_dh[0][0][i] = hv; g_dh[1][0][i] = hv;
    g_dc[0][i]    = cv; g_dc[1][i]    = cv;
    if (i < BB * SS) {
        int b = i >> 2, s = i & 3;
        // seq[:, -1, :]  (t = 15)
        g_dx[0][i] = speed[b * (TOBS * SS) + 15 * SS + s];
        g_dx[1][i] = pos  [b * (TOBS * SS) + 15 * SS + s];
    }
}

// ================= decoder heads: one warp per batch row =================
__global__ void dec_head_kernel(const float* __restrict__ hsp,
                                const float* __restrict__ hcr,
                                const float* __restrict__ fcW, const float* __restrict__ fcb,
                                const float* __restrict__ crW, const float* __restrict__ crb,
                                const float* __restrict__ emW, const float* __restrict__ emb,
                                float* __restrict__ out_sp, float* __restrict__ out_cr,
                                int t)
{
    __shared__ float Wsm[10][HH];
    __shared__ float bsm[10];
    int tid = threadIdx.x;
    #pragma unroll
    for (int rr = 0; rr < 10; rr++) {
        const float* src = (rr < 4) ? fcW + rr * HH
                         : (rr < 6) ? crW + (rr - 4) * HH
                                    : emW + (rr - 6) * HH;
        Wsm[rr][tid] = src[tid];
    }
    if (tid < 10)
        bsm[tid] = (tid < 4) ? fcb[tid] : (tid < 6) ? crb[tid - 4] : emb[tid - 6];
    __syncthreads();

    int lane = tid & 31;
    int b = blockIdx.x * 8 + (tid >> 5);

    // ---- speed head ----
    float v[8];
    #pragma unroll
    for (int jq = 0; jq < 8; jq++) v[jq] = hsp[(size_t)b * HH + lane + jq * 32];
    float dsp[4];
    #pragma unroll
    for (int r = 0; r < 4; r++) {
        float p = 0.0f;
        #pragma unroll
        for (int jq = 0; jq < 8; jq++) p += v[jq] * Wsm[r][lane + jq * 32];
        #pragma unroll
        for (int o = 16; o; o >>= 1) p += __shfl_xor_sync(0xffffffffu, p, o);
        dsp[r] = p;
    }
    if (lane < 4) {
        float ov = fminf(fmaxf(dsp[lane] + bsm[lane], -100.0f), 100.0f);
        out_sp[(size_t)b * (TOUT * SS) + t * SS + lane] = ov;
        g_dx[0][b * SS + lane] = ov;   // feedback to speed decoder
    }

    // ---- crossing head ----
    float u[8];
    #pragma unroll
    for (int jq = 0; jq < 8; jq++) u[jq] = hcr[(size_t)b * HH + lane + jq * 32];
    float dcr[6];
    #pragma unroll
    for (int r = 0; r < 6; r++) {
        float p = 0.0f;
        #pragma unroll
        for (int jq = 0; jq < 8; jq++) p += u[jq] * Wsm[4 + r][lane + jq * 32];
        #pragma unroll
        for (int o = 16; o; o >>= 1) p += __shfl_xor_sync(0xffffffffu, p, o);
        dcr[r] = p;
    }
    float l0 = fmaxf(dcr[0] + bsm[4], 0.0f);
    float l1 = fmaxf(dcr[1] + bsm[5], 0.0f);
    float mx = fmaxf(l0, l1);
    float e0 = __expf(l0 - mx), e1 = __expf(l1 - mx);
    float inv = 1.0f / (e0 + e1);
    if (lane == 0) {
        out_cr[(size_t)b * (TOUT * 2) + t * 2 + 0] = e0 * inv;
        out_cr[(size_t)b * (TOUT * 2) + t * 2 + 1] = e1 * inv;
    }
    if (lane < 4) {
        g_dx[1][b * SS + lane] = fmaxf(dcr[2 + lane] + bsm[6 + lane], 0.0f);
    }
}

// =========================== host orchestration ===========================
extern "C" void kernel_launch(void* const* d_in, const int* in_sizes, int n_in,
                              void* d_out, int out_size)
{
    const float* speed   = (const float*)d_in[0];
    const float* pos     = (const float*)d_in[1];
    const float* sp_Wih  = (const float*)d_in[2];
    const float* sp_Whh  = (const float*)d_in[3];
    const float* sp_bih  = (const float*)d_in[4];
    const float* sp_bhh  = (const float*)d_in[5];
    const float* po_Wih  = (const float*)d_in[6];
    const float* po_Whh  = (const float*)d_in[7];
    const float* po_bih  = (const float*)d_in[8];
    const float* po_bhh  = (const float*)d_in[9];
    const float* dsp_Wih = (const float*)d_in[10];
    const float* dsp_Whh = (const float*)d_in[11];
    const float* dsp_bih = (const float*)d_in[12];
    const float* dsp_bhh = (const float*)d_in[13];
    const float* dcr_Wih = (const float*)d_in[14];
    const float* dcr_Whh = (const float*)d_in[15];
    const float* dcr_bih = (const float*)d_in[16];
    const float* dcr_bhh = (const float*)d_in[17];
    const float* fcW     = (const float*)d_in[18];
    const float* fcb     = (const float*)d_in[19];
    const float* crW     = (const float*)d_in[20];
    const float* crb     = (const float*)d_in[21];
    const float* emW     = (const float*)d_in[22];
    const float* emb     = (const float*)d_in[23];

    float *eh, *ec, *dh, *dc, *dx;
    cudaGetSymbolAddress((void**)&eh, g_eh);
    cudaGetSymbolAddress((void**)&ec, g_ec);
    cudaGetSymbolAddress((void**)&dh, g_dh);
    cudaGetSymbolAddress((void**)&dc, g_dc);
    cudaGetSymbolAddress((void**)&dx, g_dx);

    float* out_sp = (float*)d_out;
    float* out_cr = out_sp + (size_t)BB * TOUT * SS;

    const dim3 sgrid(HH / NT, BB / MT, 2);   // (4, 256, 2)

    // 1) zero encoder initial state (h ping0, c)
    zero_state_kernel<<<BH / NTH, NTH>>>(eh + 0 * BH, eh + 2 * BH,
                                         ec + 0 * BH, ec + 1 * BH);

    // 2) encoders, 16 steps, both nets per launch
    for (int t = 0; t < TOBS; t++) {
        int pi = t & 1, po_ = (t + 1) & 1;
        Net a0 = { sp_Wih, sp_Whh, sp_bih, sp_bhh,
                   speed + t * SS, TOBS * SS,
                   eh + (0 * 2 + pi) * BH, ec + 0 * BH, eh + (0 * 2 + po_) * BH };
        Net a1 = { po_Wih, po_Whh, po_bih, po_bhh,
                   pos + t * SS, TOBS * SS,
                   eh + (1 * 2 + pi) * BH, ec + 1 * BH, eh + (1 * 2 + po_) * BH };
        lstm_step_kernel<<<sgrid, NTH>>>(a0, a1);
    }

    // 3) combine into decoder state + seed feedback inputs
    combine_kernel<<<BH / NTH, NTH>>>(speed, pos);

    // 4) decoders, 16 steps (step + head per step)
    for (int t = 0; t < TOUT; t++) {
        int pi = t & 1, po_ = (t + 1) & 1;
        Net a0 = { dsp_Wih, dsp_Whh, dsp_bih, dsp_bhh,
                   dx + 0 * (BB * SS), SS,
                   dh + (0 * 2 + pi) * BH, dc + 0 * BH, dh + (0 * 2 + po_) * BH };
        Net a1 = { dcr_Wih, dcr_Whh, dcr_bih, dcr_bhh,
                   dx + 1 * (BB * SS), SS,
                   dh + (1 * 2 + pi) * BH, dc + 1 * BH, dh + (1 * 2 + po_) * BH };
        lstm_step_kernel<<<sgrid, NTH>>>(a0, a1);

        dec_head_kernel<<<BB / 8, NTH>>>(dh + (0 * 2 + po_) * BH,
                                         dh + (1 * 2 + po_) * BH,
                                         fcW, fcb, crW, crb, emW, emb,
                                         out_sp, out_cr, t);
    }
}

// round 11
// speedup vs baseline: 1.9573x; 1.9573x over previous
#include <cuda_runtime.h>
#include <cuda_bf16.h>
#include <cstdint>

// ---------------- problem constants ----------------
#define BB   16384
#define HH   256
#define SS   4
#define TOBS 16
#define TOUT 16
#define BH   (BB * HH)

// ---------------- mma tiling ----------------
#define MT    128             // batch rows per CTA
#define NHID  64              // hidden cols per CTA -> 256 packed gate cols
#define NPACK 256
#define KC    64              // K chunk
#define NTH   512             // 16 warps: 4 row-groups x 4 col-groups
#define LDT   72              // smem row stride in bf16 elems (144B)

// dynamic smem layout (bytes)
#define AHI_OFF 0
#define ALO_OFF 18432         // 128*72*2
#define BHI_OFF 36864
#define BLO_OFF 73728         // BHI + 256*72*2/...  (B tile = 36864B)
#define DYN_BYTES 110592

__device__ __forceinline__ uint32_t smem_u32(const void* p) {
    uint32_t a;
    asm("{ .reg .u64 t; cvta.to.shared.u64 t, %1; cvt.u32.u64 %0, t; }" : "=r"(a) : "l"(p));
    return a;
}

__device__ __forceinline__ void ldsm4(uint32_t (&r)[4], uint32_t addr) {
    asm volatile("ldmatrix.sync.aligned.m8n8.x4.shared.b16 {%0,%1,%2,%3}, [%4];"
                 : "=r"(r[0]), "=r"(r[1]), "=r"(r[2]), "=r"(r[3]) : "r"(addr));
}

__device__ __forceinline__ void mma_bf16(float (&d)[4], const uint32_t (&a)[4],
                                         uint32_t b0, uint32_t b1) {
    asm volatile("mma.sync.aligned.m16n8k16.row.col.f32.bf16.bf16.f32 "
                 "{%0,%1,%2,%3}, {%4,%5,%6,%7}, {%8,%9}, {%0,%1,%2,%3};"
                 : "+f"(d[0]), "+f"(d[1]), "+f"(d[2]), "+f"(d[3])
                 : "r"(a[0]), "r"(a[1]), "r"(a[2]), "r"(a[3]), "r"(b0), "r"(b1));
}

// ---------------- device scratch ----------------
__device__ __nv_bfloat16 g_hhi[2][2][BH];
__device__ __nv_bfloat16 g_hlo[2][2][BH];
__device__ float         g_c[2][BH];
__device__ __nv_bfloat16 g_whi[4][1024 * HH];
__device__ __nv_bfloat16 g_wlo[4][1024 * HH];
__device__ float         g_dx[2][BB * SS];

struct NetT {
    const float* __restrict__ Wih;
    const float* __restrict__ bih;
    const float* __restrict__ bhh;
    const __nv_bfloat16* __restrict__ whh_hi;
    const __nv_bfloat16* __restrict__ whh_lo;
    const float* __restrict__ x;
    int xstride;
    const __nv_bfloat16* __restrict__ h_in_hi;
    const __nv_bfloat16* __restrict__ h_in_lo;
    float* __restrict__ c;
    __nv_bfloat16* __restrict__ h_out_hi;
    __nv_bfloat16* __restrict__ h_out_lo;
};

__device__ __forceinline__ float sigf(float x) { return 1.0f / (1.0f + __expf(-x)); }
__device__ __forceinline__ float tanh_acc(float x) { return 2.0f / (1.0f + __expf(-2.0f * x)) - 1.0f; }

// =================== HMMA fused LSTM step ===================
// G = h@Whh^T (3-pass bf16 compensated) + x@Wih^T + b; then LSTM cell.
// Packed gate col p (0..255): ht=p>>5, g=(p>>3)&3, e=p&7 -> global j = g*256 + nb0 + ht*8 + e
__global__ void __launch_bounds__(NTH, 1)
lstm_step_mma(NetT n0, NetT n1)
{
    extern __shared__ char sm[];
    NetT P = (blockIdx.z == 0) ? n0 : n1;

    __shared__ float4 WihS[NPACK];
    __shared__ float  biasS[NPACK];

    const int tid  = threadIdx.x;
    const int wid  = tid >> 5;
    const int lane = tid & 31;
    const int wr   = wid & 3;        // row group (32 rows)
    const int wc   = wid >> 2;       // col group (64 packed cols)
    const int m0   = blockIdx.y * MT;
    const int nb0  = blockIdx.x * NHID;

    if (tid < NPACK) {
        int p = tid;
        int ht = p >> 5, g = (p >> 3) & 3, e = p & 7;
        int j = g * 256 + nb0 + ht * 8 + e;
        WihS[p]  = *(const float4*)(P.Wih + j * 4);
        biasS[p] = P.bih[j] + P.bhh[j];
    }

    const uint32_t smb = smem_u32(sm);

    float acc[2][8][4];
    #pragma unroll
    for (int a = 0; a < 2; a++)
        #pragma unroll
        for (int b = 0; b < 8; b++)
            #pragma unroll
            for (int q = 0; q < 4; q++) acc[a][b][q] = 0.0f;

    for (int c = 0; c < 4; c++) {
        const int kb = c * KC;
        __syncthreads();
        // stage A (h hi/lo): 128 rows x 64 bf16
        #pragma unroll
        for (int i = 0; i < 2; i++) {
            int u = i * NTH + tid;
            int r = u >> 3, s = u & 7;
            int off = r * 144 + s * 16;
            size_t go = (size_t)(m0 + r) * HH + kb + s * 8;
            *(uint4*)(sm + AHI_OFF + off) = *(const uint4*)(P.h_in_hi + go);
            *(uint4*)(sm + ALO_OFF + off) = *(const uint4*)(P.h_in_lo + go);
        }
        // stage B (Whh hi/lo): 256 packed rows x 64 bf16
        #pragma unroll
        for (int i = 0; i < 4; i++) {
            int u = i * NTH + tid;
            int r = u >> 3, s = u & 7;
            int ht = r >> 5, g = (r >> 3) & 3, e = r & 7;
            int j = g * 256 + nb0 + ht * 8 + e;
            int off = r * 144 + s * 16;
            size_t go = (size_t)j * HH + kb + s * 8;
            *(uint4*)(sm + BHI_OFF + off) = *(const uint4*)(P.whh_hi + go);
            *(uint4*)(sm + BLO_OFF + off) = *(const uint4*)(P.whh_lo + go);
        }
        __syncthreads();

        #pragma unroll
        for (int kk = 0; kk < 4; kk++) {
            const int kby = (kk * 16 + (lane >> 4) * 8) * 2;   // k byte offset in tile
            const int ar0 = (wr * 32 + (lane & 15)) * 144;
            const int ar1 = ar0 + 16 * 144;

            uint32_t Ah0[4], Ah1[4], Al0[4], Al1[4];
            ldsm4(Ah0, smb + AHI_OFF + ar0 + kby);
            ldsm4(Ah1, smb + AHI_OFF + ar1 + kby);
            ldsm4(Al0, smb + ALO_OFF + ar0 + kby);
            ldsm4(Al1, smb + ALO_OFF + ar1 + kby);

            uint32_t Bh[4][4];
            #pragma unroll
            for (int np = 0; np < 4; np++) {
                int br = (wc * 64 + np * 16 + (lane & 15)) * 144;
                ldsm4(Bh[np], smb + BHI_OFF + br + kby);
            }
            // pass 0: Ah x Bh
            #pragma unroll
            for (int np = 0; np < 4; np++) {
                mma_bf16(acc[0][2 * np],     Ah0, Bh[np][0], Bh[np][2]);
                mma_bf16(acc[0][2 * np + 1], Ah0, Bh[np][1], Bh[np][3]);
                mma_bf16(acc[1][2 * np],     Ah1, Bh[np][0], Bh[np][2]);
                mma_bf16(acc[1][2 * np + 1], Ah1, Bh[np][1], Bh[np][3]);
            }
            // pass 1: Ah x Bl (streamed)
            #pragma unroll
            for (int np = 0; np < 4; np++) {
                uint32_t Bl[4];
                int br = (wc * 64 + np * 16 + (lane & 15)) * 144;
                ldsm4(Bl, smb + BLO_OFF + br + kby);
                mma_bf16(acc[0][2 * np],     Ah0, Bl[0], Bl[2]);
                mma_bf16(acc[0][2 * np + 1], Ah0, Bl[1], Bl[3]);
                mma_bf16(acc[1][2 * np],     Ah1, Bl[0], Bl[2]);
                mma_bf16(acc[1][2 * np + 1], Ah1, Bl[1], Bl[3]);
            }
            // pass 2: Al x Bh
            #pragma unroll
            for (int np = 0; np < 4; np++) {
                mma_bf16(acc[0][2 * np],     Al0, Bh[np][0], Bh[np][2]);
                mma_bf16(acc[0][2 * np + 1], Al0, Bh[np][1], Bh[np][3]);
                mma_bf16(acc[1][2 * np],     Al1, Bh[np][0], Bh[np][2]);
                mma_bf16(acc[1][2 * np + 1], Al1, Bh[np][1], Bh[np][3]);
            }
        }
    }

    // ---- epilogue: + x@Wih^T + bias, LSTM cell, write c / h(hi,lo) ----
    const int l4 = lane >> 2;
    const int e0 = (lane & 3) * 2;
    #pragma unroll
    for (int rb = 0; rb < 2; rb++) {
        #pragma unroll
        for (int cp = 0; cp < 2; cp++) {
            const int row = m0 + wr * 32 + rb * 16 + cp * 8 + l4;
            float4 xr = *(const float4*)(P.x + (size_t)row * P.xstride);
            float*         crow = P.c        + (size_t)row * HH + nb0;
            __nv_bfloat16* hhp  = P.h_out_hi + (size_t)row * HH + nb0;
            __nv_bfloat16* hlp  = P.h_out_lo + (size_t)row * HH + nb0;
            #pragma unroll
            for (int htl = 0; htl < 2; htl++) {
                const int hcol = (wc * 2 + htl) * 8 + e0;
                float2 cold = *(float2*)(crow + hcol);
                float g4[4][2];
                #pragma unroll
                for (int g = 0; g < 4; g++) {
                    const int jn = htl * 4 + g;
                    const int p0 = (wc * 2 + htl) * 32 + g * 8 + e0;
                    #pragma unroll
                    for (int e = 0; e < 2; e++) {
                        float4 wi = WihS[p0 + e];
                        g4[g][e] = acc[rb][jn][cp * 2 + e] + biasS[p0 + e]
                                 + xr.x * wi.x + xr.y * wi.y + xr.z * wi.z + xr.w * wi.w;
                    }
                }
                float cv[2] = {cold.x, cold.y};
                float hn[2];
                #pragma unroll
                for (int e = 0; e < 2; e++) {
                    float cn = sigf(g4[1][e]) * cv[e] + sigf(g4[0][e]) * tanh_acc(g4[2][e]);
                    hn[e] = sigf(g4[3][e]) * tanh_acc(cn);
                    cv[e] = cn;
                }
                *(float2*)(crow + hcol) = make_float2(cv[0], cv[1]);
                __nv_bfloat162 hp, lp;
                hp.x = __float2bfloat16_rn(hn[0]);
                hp.y = __float2bfloat16_rn(hn[1]);
                lp.x = __float2bfloat16_rn(hn[0] - __bfloat162float(hp.x));
                lp.y = __float2bfloat16_rn(hn[1] - __bfloat162float(hp.y));
                *(__nv_bfloat162*)(hhp + hcol) = hp;
                *(__nv_bfloat162*)(hlp + hcol) = lp;
            }
        }
    }
}

// =================== weight split (once per launch) ===================
__global__ void split_whh_kernel(const float* __restrict__ w0, const float* __restrict__ w1,
                                 const float* __restrict__ w2, const float* __restrict__ w3)
{
    int idx = blockIdx.x * blockDim.x + threadIdx.x;       // 4 * 262144
    int net = idx >> 18;
    int r   = idx & 0x3FFFF;
    const float* src = (net == 0) ? w0 : (net == 1) ? w1 : (net == 2) ? w2 : w3;
    float w = src[r];
    __nv_bfloat16 hi = __float2bfloat16_rn(w);
    (&g_whi[0][0])[idx] = hi;
    (&g_wlo[0][0])[idx] = __float2bfloat16_rn(w - __bfloat162float(hi));
}

// =================== zero encoder initial state ===================
__global__ void zero_state_kernel()
{
    int i = blockIdx.x * blockDim.x + threadIdx.x;
    __nv_bfloat16 z = __float2bfloat16_rn(0.0f);
    g_hhi[0][0][i] = z; g_hlo[0][0][i] = z;
    g_hhi[1][0][i] = z; g_hlo[1][0][i] = z;
    g_c[0][i] = 0.0f;   g_c[1][i] = 0.0f;
}

// =================== combine encoder -> decoder init ===================
__global__ void combine_kernel(const float* __restrict__ speed,
                               const float* __restrict__ pos)
{
    int i = blockIdx.x * blockDim.x + threadIdx.x;
    float h0 = __bfloat162float(g_hhi[0][0][i]) + __bfloat162float(g_hlo[0][0][i]);
    float h1 = __bfloat162float(g_hhi[1][0][i]) + __bfloat162float(g_hlo[1][0][i]);
    float hs = h0 + h1;
    float cs = g_c[0][i] + g_c[1][i];
    __nv_bfloat16 hh = __float2bfloat16_rn(hs);
    __nv_bfloat16 hl = __float2bfloat16_rn(hs - __bfloat162float(hh));
    g_hhi[0][0][i] = hh; g_hlo[0][0][i] = hl;
    g_hhi[1][0][i] = hh; g_hlo[1][0][i] = hl;
    g_c[0][i] = cs;      g_c[1][i] = cs;
    if (i < BB * SS) {
        int b = i >> 2, s = i & 3;
        g_dx[0][i] = speed[b * (TOBS * SS) + 15 * SS + s];
        g_dx[1][i] = pos  [b * (TOBS * SS) + 15 * SS + s];
    }
}

// =================== decoder heads ===================
__global__ void dec_head_kernel(const __nv_bfloat16* __restrict__ hsp_hi,
                                const __nv_bfloat16* __restrict__ hsp_lo,
                                const __nv_bfloat16* __restrict__ hcr_hi,
                                const __nv_bfloat16* __restrict__ hcr_lo,
                                const float* __restrict__ fcW, const float* __restrict__ fcb,
                                const float* __restrict__ crW, const float* __restrict__ crb,
                                const float* __restrict__ emW, const float* __restrict__ emb,
                                float* __restrict__ out_sp, float* __restrict__ out_cr,
                                int t)
{
    __shared__ float Wsm[10][HH];
    __shared__ float bsm[10];
    int tid = threadIdx.x;
    #pragma unroll
    for (int rr = 0; rr < 10; rr++) {
        const float* src = (rr < 4) ? fcW + rr * HH
                         : (rr < 6) ? crW + (rr - 4) * HH
                                    : emW + (rr - 6) * HH;
        Wsm[rr][tid] = src[tid];
    }
    if (tid < 10)
        bsm[tid] = (tid < 4) ? fcb[tid] : (tid < 6) ? crb[tid - 4] : emb[tid - 6];
    __syncthreads();

    int lane = tid & 31;
    int b = blockIdx.x * 8 + (tid >> 5);

    float v[8];
    #pragma unroll
    for (int jq = 0; jq < 8; jq++) {
        size_t ix = (size_t)b * HH + lane + jq * 32;
        v[jq] = __bfloat162float(hsp_hi[ix]) + __bfloat162float(hsp_lo[ix]);
    }
    float dsp[4];
    #pragma unroll
    for (int r = 0; r < 4; r++) {
        float p = 0.0f;
        #pragma unroll
        for (int jq = 0; jq < 8; jq++) p += v[jq] * Wsm[r][lane + jq * 32];
        #pragma unroll
        for (int o = 16; o; o >>= 1) p += __shfl_xor_sync(0xffffffffu, p, o);
        dsp[r] = p;
    }
    if (lane < 4) {
        float ov = fminf(fmaxf(dsp[lane] + bsm[lane], -100.0f), 100.0f);
        out_sp[(size_t)b * (TOUT * SS) + t * SS + lane] = ov;
        g_dx[0][b * SS + lane] = ov;
    }

    float u[8];
    #pragma unroll
    for (int jq = 0; jq < 8; jq++) {
        size_t ix = (size_t)b * HH + lane + jq * 32;
        u[jq] = __bfloat162float(hcr_hi[ix]) + __bfloat162float(hcr_lo[ix]);
    }
    float dcr[6];
    #pragma unroll
    for (int r = 0; r < 6; r++) {
        float p = 0.0f;
        #pragma unroll
        for (int jq = 0; jq < 8; jq++) p += u[jq] * Wsm[4 + r][lane + jq * 32];
        #pragma unroll
        for (int o = 16; o; o >>= 1) p += __shfl_xor_sync(0xffffffffu, p, o);
        dcr[r] = p;
    }
    float l0 = fmaxf(dcr[0] + bsm[4], 0.0f);
    float l1 = fmaxf(dcr[1] + bsm[5], 0.0f);
    float mx = fmaxf(l0, l1);
    float e0 = __expf(l0 - mx), e1 = __expf(l1 - mx);
    float inv = 1.0f / (e0 + e1);
    if (lane == 0) {
        out_cr[(size_t)b * (TOUT * 2) + t * 2 + 0] = e0 * inv;
        out_cr[(size_t)b * (TOUT * 2) + t * 2 + 1] = e1 * inv;
    }
    if (lane < 4) {
        g_dx[1][b * SS + lane] = fmaxf(dcr[2 + lane] + bsm[6 + lane], 0.0f);
    }
}

// =========================== host orchestration ===========================
extern "C" void kernel_launch(void* const* d_in, const int* in_sizes, int n_in,
                              void* d_out, int out_size)
{
    const float* speed   = (const float*)d_in[0];
    const float* pos     = (const float*)d_in[1];
    const float* sp_Wih  = (const float*)d_in[2];
    const float* sp_Whh  = (const float*)d_in[3];
    const float* sp_bih  = (const float*)d_in[4];
    const float* sp_bhh  = (const float*)d_in[5];
    const float* po_Wih  = (const float*)d_in[6];
    const float* po_Whh  = (const float*)d_in[7];
    const float* po_bih  = (const float*)d_in[8];
    const float* po_bhh  = (const float*)d_in[9];
    const float* dsp_Wih = (const float*)d_in[10];
    const float* dsp_Whh = (const float*)d_in[11];
    const float* dsp_bih = (const float*)d_in[12];
    const float* dsp_bhh = (const float*)d_in[13];
    const float* dcr_Wih = (const float*)d_in[14];
    const float* dcr_Whh = (const float*)d_in[15];
    const float* dcr_bih = (const float*)d_in[16];
    const float* dcr_bhh = (const float*)d_in[17];
    const float* fcW     = (const float*)d_in[18];
    const float* fcb     = (const float*)d_in[19];
    const float* crW     = (const float*)d_in[20];
    const float* crb     = (const float*)d_in[21];
    const float* emW     = (const float*)d_in[22];
    const float* emb     = (const float*)d_in[23];

    cudaFuncSetAttribute(lstm_step_mma,
                         cudaFuncAttributeMaxDynamicSharedMemorySize, DYN_BYTES);

    __nv_bfloat16 *hhi, *hlo, *whi, *wlo;
    float *cc, *dx;
    cudaGetSymbolAddress((void**)&hhi, g_hhi);
    cudaGetSymbolAddress((void**)&hlo, g_hlo);
    cudaGetSymbolAddress((void**)&cc,  g_c);
    cudaGetSymbolAddress((void**)&whi, g_whi);
    cudaGetSymbolAddress((void**)&wlo, g_wlo);
    cudaGetSymbolAddress((void**)&dx,  g_dx);

    float* out_sp = (float*)d_out;
    float* out_cr = out_sp + (size_t)BB * TOUT * SS;

    const int WSZ = 1024 * HH;

    split_whh_kernel<<<(4 * WSZ) / 256, 256>>>(sp_Whh, po_Whh, dsp_Whh, dcr_Whh);
    zero_state_kernel<<<BH / 256, 256>>>();

    const dim3 sgrid(HH / NHID, BB / MT, 2);   // (4, 128, 2)

    for (int t = 0; t < TOBS; t++) {
        int pi = t & 1, po_ = (t + 1) & 1;
        NetT a0 = { sp_Wih, sp_bih, sp_bhh, whi + 0 * WSZ, wlo + 0 * WSZ,
                    speed + t * SS, TOBS * SS,
                    hhi + (0 * 2 + pi) * (size_t)BH, hlo + (0 * 2 + pi) * (size_t)BH,
                    cc + 0 * (size_t)BH,
                    hhi + (0 * 2 + po_) * (size_t)BH, hlo + (0 * 2 + po_) * (size_t)BH };
        NetT a1 = { po_Wih, po_bih, po_bhh, whi + 1 * WSZ, wlo + 1 * WSZ,
                    pos + t * SS, TOBS * SS,
                    hhi + (1 * 2 + pi) * (size_t)BH, hlo + (1 * 2 + pi) * (size_t)BH,
                    cc + 1 * (size_t)BH,
                    hhi + (1 * 2 + po_) * (size_t)BH, hlo + (1 * 2 + po_) * (size_t)BH };
        lstm_step_mma<<<sgrid, NTH, DYN_BYTES>>>(a0, a1);
    }

    combine_kernel<<<BH / 256, 256>>>(speed, pos);

    for (int t = 0; t < TOUT; t++) {
        int pi = t & 1, po_ = (t + 1) & 1;
        NetT a0 = { dsp_Wih, dsp_bih, dsp_bhh, whi + 2 * WSZ, wlo + 2 * WSZ,
                    dx + 0 * (BB * SS), SS,
                    hhi + (0 * 2 + pi) * (size_t)BH, hlo + (0 * 2 + pi) * (size_t)BH,
                    cc + 0 * (size_t)BH,
                    hhi + (0 * 2 + po_) * (size_t)BH, hlo + (0 * 2 + po_) * (size_t)BH };
        NetT a1 = { dcr_Wih, dcr_bih, dcr_bhh, whi + 3 * WSZ, wlo + 3 * WSZ,
                    dx + 1 * (BB * SS), SS,
                    hhi + (1 * 2 + pi) * (size_t)BH, hlo + (1 * 2 + pi) * (size_t)BH,
                    cc + 1 * (size_t)BH,
                    hhi + (1 * 2 + po_) * (size_t)BH, hlo + (1 * 2 + po_) * (size_t)BH };
        lstm_step_mma<<<sgrid, NTH, DYN_BYTES>>>(a0, a1);

        dec_head_kernel<<<BB / 8, 256>>>(hhi + (0 * 2 + po_) * (size_t)BH,
                                         hlo + (0 * 2 + po_) * (size_t)BH,
                                         hhi + (1 * 2 + po_) * (size_t)BH,
                                         hlo + (1 * 2 + po_) * (size_t)BH,
                                         fcW, fcb, crW, crb, emW, emb,
                                         out_sp, out_cr, t);
    }
}